// round 15
// baseline (speedup 1.0000x reference)
#include <cuda_runtime.h>
#include <cuda_fp16.h>
#include <math.h>

#define T_SEQ 2048
#define DIM_   1024
#define NH     8
#define HD     128
#define RMS_EPS 1.1920929e-7f
#define C_SC (0.12f * 1.4426950408889634f)   // ATTN_SCALE * log2(e)

// -------------------- scratch (static device globals; no allocs) --------------------
__device__ __half g_xh   [(size_t)T_SEQ * DIM_];      // fp16 x
__device__ __half g_wqkv [(size_t)3 * DIM_ * DIM_];   // fp16 qkv_w
__device__ __half g_wproj[(size_t)DIM_ * DIM_];       // fp16 c_proj_w
__device__ __half g_qh   [(size_t)NH * T_SEQ * HD];   // [h][t][d]  (pre-scaled by C_SC)
__device__ __half g_kh   [(size_t)NH * T_SEQ * HD];   // [h][t][d]
__device__ __half g_vt   [(size_t)NH * HD * T_SEQ];   // [h][d][t]
__device__ __half g_yh   [(size_t)T_SEQ * DIM_];      // attention out, fp16
__device__ float  g_rot  [(size_t)T_SEQ * 64];        // [t][2j]=cos, [t][2j+1]=sin, j<32
__device__ float  g_fr   [32];                        // rotary frequencies

// -------------------- helpers --------------------------------------------------------
__device__ __forceinline__ uint2 f4h(float4 v) {
    uint2 r;
    asm("cvt.rn.f16x2.f32 %0, %1, %2;" : "=r"(r.x) : "f"(v.y), "f"(v.x));
    asm("cvt.rn.f16x2.f32 %0, %1, %2;" : "=r"(r.y) : "f"(v.w), "f"(v.z));
    return r;
}
__device__ __forceinline__ unsigned packh2(float lo, float hi) {
    unsigned r;
    asm("cvt.rn.f16x2.f32 %0, %1, %2;" : "=r"(r) : "f"(hi), "f"(lo));
    return r;
}
__device__ __forceinline__ void mma_h(float c[4], const unsigned a[4], const unsigned* b) {
    asm volatile(
        "mma.sync.aligned.m16n8k16.row.col.f32.f16.f16.f32 "
        "{%0,%1,%2,%3}, {%4,%5,%6,%7}, {%8,%9}, {%0,%1,%2,%3};"
        : "+f"(c[0]), "+f"(c[1]), "+f"(c[2]), "+f"(c[3])
        : "r"(a[0]), "r"(a[1]), "r"(a[2]), "r"(a[3]), "r"(b[0]), "r"(b[1]));
}
__device__ __forceinline__ void ldm4(unsigned r[4], unsigned addr) {
    asm volatile("ldmatrix.sync.aligned.m8n8.x4.shared.b16 {%0,%1,%2,%3}, [%4];"
                 : "=r"(r[0]), "=r"(r[1]), "=r"(r[2]), "=r"(r[3]) : "r"(addr));
}
__device__ __forceinline__ unsigned smem_u32(const void* p) {
    unsigned a;
    asm("{.reg .u64 t; cvta.to.shared.u64 t, %1; cvt.u32.u64 %0, t;}" : "=r"(a) : "l"(p));
    return a;
}
__device__ __forceinline__ void cpa16(unsigned dst, const void* src) {
    asm volatile("cp.async.cg.shared.global [%0], [%1], 16;" :: "r"(dst), "l"(src) : "memory");
}
__device__ __forceinline__ void cp_commit() { asm volatile("cp.async.commit_group;" ::: "memory"); }
__device__ __forceinline__ void cp_wait0()  { asm volatile("cp.async.wait_group 0;" ::: "memory"); }
__device__ __forceinline__ void cp_wait1()  { asm volatile("cp.async.wait_group 1;" ::: "memory"); }

// -------------------- fused prep: fp32->fp16 x/w_qkv/w_proj + fr table ----------------
__global__ __launch_bounds__(256)
void prep(const float* __restrict__ x, const float* __restrict__ qkv_w,
          const float* __restrict__ c_proj_w)
{
    const int b = blockIdx.x;
    const float* s;
    __half* d;
    int base;
    if (b < 1024)      { s = x;        d = g_xh;    base = b; }
    else if (b < 2560) { s = qkv_w;    d = g_wqkv;  base = b - 1024; }
    else if (b < 3072) { s = c_proj_w; d = g_wproj; base = b - 2560; }
    else {
        if (threadIdx.x < 32) {
            float tj = (float)threadIdx.x / 31.0f;
            g_fr[threadIdx.x] = (float)exp2(-10.0 * (double)tj);  // bit-identical fr
        }
        return;
    }
    int i = (base * 256 + threadIdx.x) * 8;
    float4 a = *(const float4*)(s + i);
    float4 c = *(const float4*)(s + i + 4);
    uint2 ua = f4h(a), uc = f4h(c);
    *(uint4*)(d + i) = make_uint4(ua.x, ua.y, uc.x, uc.y);
}

// -------------------- rotary table: fp32 Cody-Waite sincos ---------------------------
__global__ __launch_bounds__(256)
void rot_build()
{
    int idx = blockIdx.x * 256 + threadIdx.x;
    int t = idx >> 5, j = idx & 31;
    float th = (float)t * g_fr[j];

    const float C1 = 1.5703125f;
    const float C2 = 4.83826794897e-4f;
    float kf = rintf(th * 0.63661977236758134f);
    int   ki = (int)kf;
    float r  = fmaf(-kf, C1, th);
    r = fmaf(-kf, C2, r);

    float r2 = r * r;
    float sp = fmaf(r2, fmaf(r2, fmaf(r2, 2.75573137e-6f, -1.98412698e-4f),
                             8.33333376e-3f), -1.66666672e-1f);
    sp = fmaf(r * r2, sp, r);
    float cp = fmaf(r2, fmaf(r2, fmaf(r2, fmaf(r2, 2.44331571e-5f, -1.38873162e-3f),
                             4.16666418e-2f), -0.5f), 1.0f);

    float cosv, sinv;
    switch (ki & 3) {
        case 0:  cosv =  cp; sinv =  sp; break;
        case 1:  cosv = -sp; sinv =  cp; break;
        case 2:  cosv = -cp; sinv = -sp; break;
        default: cosv =  sp; sinv = -cp; break;
    }
    g_rot[t * 64 + 2 * j]     = cosv;
    g_rot[t * 64 + 2 * j + 1] = sinv;
}

// -------------------- fused QKV GEMM + rmsnorm/rotary/vmix epilogue ------------------
#define G3_STAGE 9216
#define GEMM_SMEM_BYTES (2 * G3_STAGE * 4)

__global__ __launch_bounds__(256, 2)
void gemm_qkv(const __half* __restrict__ A, const __half* __restrict__ B,
              const float* __restrict__ ve, const float* __restrict__ lambdas)
{
    extern __shared__ unsigned gsm[];
    const unsigned smb = smem_u32(gsm);
    const int tid  = threadIdx.x;
    const int lane = tid & 31;
    const int wid  = tid >> 5;
    const int wm   = wid >> 2;
    const int wn   = wid & 3;
    const int m0   = blockIdx.y * 128;
    const int n0   = blockIdx.x * 128;
    const int type = blockIdx.x >> 3;
    const int head = blockIdx.x & 7;
    const int K    = DIM_;
    const int rq   = lane >> 2, cq = lane & 3;

    const int arow = (lane & 7) + ((lane >> 3) & 1) * 8;
    const int acol = (lane >> 4) * 4;
    const int brow = (lane & 7) + ((lane >> 4) & 1) * 8;
    const int bcol = ((lane >> 3) & 1) * 4;
    const int NK   = K >> 6;

    auto loadAB = [&](int it, int s) {
        const __half* Ab = A + (size_t)m0 * K + it * 64;
        const __half* Bb = B + (size_t)n0 * K + it * 64;
        unsigned da = smb + s * (G3_STAGE * 4);
        unsigned db = da + 4608 * 4;
#pragma unroll
        for (int p = 0; p < 4; p++) {
            int id = tid + p * 256;
            int row = id >> 3, o = id & 7;
            cpa16(da + row * 144u + o * 16u, Ab + (size_t)row * K + o * 8);
        }
#pragma unroll
        for (int p = 0; p < 4; p++) {
            int id = tid + p * 256;
            int row = id >> 3, o = id & 7;
            cpa16(db + row * 144u + o * 16u, Bb + (size_t)row * K + o * 8);
        }
    };

    float acc[4][4][4];
#pragma unroll
    for (int i = 0; i < 4; i++)
#pragma unroll
        for (int j = 0; j < 4; j++)
#pragma unroll
            for (int r = 0; r < 4; r++) acc[i][j][r] = 0.0f;

    loadAB(0, 0); cp_commit();

    for (int it = 0; it < NK; it++) {
        const int s = it & 1;
        if (it + 1 < NK) { loadAB(it + 1, s ^ 1); cp_commit(); cp_wait1(); }
        else             { cp_wait0(); }
        __syncthreads();

        const unsigned ab = smb + s * (G3_STAGE * 4);
        const unsigned bb = ab + 4608 * 4;
#pragma unroll
        for (int ks = 0; ks < 4; ks++) {
            unsigned a[4][4], bq[2][4];
#pragma unroll
            for (int mi = 0; mi < 4; mi++)
                ldm4(a[mi], ab + ((wm * 64 + mi * 16 + arow) * 36 + ks * 8 + acol) * 4);
#pragma unroll
            for (int jp = 0; jp < 2; jp++)
                ldm4(bq[jp], bb + ((wn * 32 + jp * 16 + brow) * 36 + ks * 8 + bcol) * 4);
#pragma unroll
            for (int j = 0; j < 4; j++) {
                const unsigned* pb = &bq[j >> 1][(j & 1) * 2];
#pragma unroll
                for (int mi = 0; mi < 4; mi++)
                    mma_h(acc[mi][j], a[mi], pb);
            }
        }
        __syncthreads();
    }

    // ---------------- fused epilogue ----------------
    if (type < 2) {
        float* stageF = (float*)gsm;                 // [128][132]
        float* red    = (float*)gsm + 16896;         // [4][128]

#pragma unroll
        for (int mi = 0; mi < 4; mi++) {
            float p0 = 0.0f, p1 = 0.0f;
#pragma unroll
            for (int j = 0; j < 4; j++) {
                p0 = fmaf(acc[mi][j][0], acc[mi][j][0], p0);
                p0 = fmaf(acc[mi][j][1], acc[mi][j][1], p0);
                p1 = fmaf(acc[mi][j][2], acc[mi][j][2], p1);
                p1 = fmaf(acc[mi][j][3], acc[mi][j][3], p1);
            }
            p0 += __shfl_xor_sync(0xffffffffu, p0, 1);
            p0 += __shfl_xor_sync(0xffffffffu, p0, 2);
            p1 += __shfl_xor_sync(0xffffffffu, p1, 1);
            p1 += __shfl_xor_sync(0xffffffffu, p1, 2);
            if (cq == 0) {
                int row = wm * 64 + mi * 16 + rq;
                red[wn * 128 + row]     = p0;
                red[wn * 128 + row + 8] = p1;
            }
        }
        __syncthreads();

#pragma unroll
        for (int mi = 0; mi < 4; mi++) {
            int row0 = wm * 64 + mi * 16 + rq;
            float s0 = red[row0] + red[128 + row0] + red[256 + row0] + red[384 + row0];
            float s1 = red[row0 + 8] + red[128 + row0 + 8] + red[256 + row0 + 8] + red[384 + row0 + 8];
            float rn0 = rsqrtf(s0 * (1.0f / 128.0f) + RMS_EPS);
            float rn1 = rsqrtf(s1 * (1.0f / 128.0f) + RMS_EPS);
#pragma unroll
            for (int j = 0; j < 4; j++) {
                acc[mi][j][0] *= rn0; acc[mi][j][1] *= rn0;
                acc[mi][j][2] *= rn1; acc[mi][j][3] *= rn1;
            }
        }
        __syncthreads();

#pragma unroll
        for (int mi = 0; mi < 4; mi++) {
            int row0 = wm * 64 + mi * 16 + rq, row1 = row0 + 8;
            int c = wn * 32 + 2 * cq;
#pragma unroll
            for (int j = 0; j < 4; j++) {
                *(float2*)&stageF[row0 * 132 + c + j * 8] = make_float2(acc[mi][j][0], acc[mi][j][1]);
                *(float2*)&stageF[row1 * 132 + c + j * 8] = make_float2(acc[mi][j][2], acc[mi][j][3]);
            }
        }
        __syncthreads();

        __half* dst = (type == 0 ? g_qh : g_kh) + (size_t)head * T_SEQ * HD;
        const float osc = (type == 0) ? C_SC : 1.0f;   // pre-scale q into log2 domain
        const bool dorot = ((wn & 1) == 0);
        const float sgn = (wn == 0) ? 1.0f : -1.0f;
#pragma unroll
        for (int mi = 0; mi < 4; mi++) {
#pragma unroll
            for (int p = 0; p < 2; p++) {
                int row_l = wm * 64 + mi * 16 + rq + p * 8;
                int row_g = m0 + row_l;
#pragma unroll
                for (int j = 0; j < 4; j++) {
                    int c = wn * 32 + j * 8 + 2 * cq;
                    float v0 = acc[mi][j][2 * p], v1 = acc[mi][j][2 * p + 1];
                    float o0 = v0, o1 = v1;
                    if (dorot) {
                        float2 pp = *(float2*)&stageF[row_l * 132 + (c ^ 64)];
                        float4 cs = *(const float4*)&g_rot[(size_t)row_g * 64 + 2 * (c & 63)];
                        o0 = fmaf(sgn * pp.x, cs.y, v0 * cs.x);
                        o1 = fmaf(sgn * pp.y, cs.w, v1 * cs.z);
                    }
                    *(unsigned*)&dst[(size_t)row_g * HD + c] = packh2(o0 * osc, o1 * osc);
                }
            }
        }
    } else {
        const float l0v = lambdas[0], l1v = lambdas[1];
        __half* tile = (__half*)gsm;                 // [128][136]
#pragma unroll
        for (int mi = 0; mi < 4; mi++) {
            int row0 = wm * 64 + mi * 16 + rq, row1 = row0 + 8;
#pragma unroll
            for (int j = 0; j < 4; j++) {
                int c = wn * 32 + j * 8 + 2 * cq;
                float2 e0 = *(const float2*)&ve[(size_t)(m0 + row0) * DIM_ + head * HD + c];
                float2 e1 = *(const float2*)&ve[(size_t)(m0 + row1) * DIM_ + head * HD + c];
                *(unsigned*)&tile[row0 * 136 + c] =
                    packh2(fmaf(l1v, e0.x, l0v * acc[mi][j][0]), fmaf(l1v, e0.y, l0v * acc[mi][j][1]));
                *(unsigned*)&tile[row1 * 136 + c] =
                    packh2(fmaf(l1v, e1.x, l0v * acc[mi][j][2]), fmaf(l1v, e1.y, l0v * acc[mi][j][3]));
            }
        }
        __syncthreads();
#pragma unroll
        for (int p = 0; p < 8; p++) {
            int id = tid + p * 256;
            int d = id >> 4, t8 = (id & 15) * 8;
            __half tmp[8];
#pragma unroll
            for (int i = 0; i < 8; i++) tmp[i] = tile[(t8 + i) * 136 + d];
            *(uint4*)&g_vt[((size_t)head * HD + d) * T_SEQ + m0 + t8] = *(uint4*)tmp;
        }
    }
}

// -------------------- plain GEMM (fp16 TC, 2-stage): C = A @ B^T (proj) --------------
__global__ __launch_bounds__(256, 2)
void gemm_h3(const __half* __restrict__ A, const __half* __restrict__ B,
             float* __restrict__ C, int M, int N, int K)
{
    extern __shared__ unsigned gsm[];
    const unsigned smb = smem_u32(gsm);
    const int tid  = threadIdx.x;
    const int lane = tid & 31;
    const int wid  = tid >> 5;
    const int wm   = wid >> 2;
    const int wn   = wid & 3;
    const int m0   = blockIdx.y * 128;
    const int n0   = blockIdx.x * 128;

    const int arow = (lane & 7) + ((lane >> 3) & 1) * 8;
    const int acol = (lane >> 4) * 4;
    const int brow = (lane & 7) + ((lane >> 4) & 1) * 8;
    const int bcol = ((lane >> 3) & 1) * 4;
    const int NK   = K >> 6;

    auto loadAB = [&](int it, int s) {
        const __half* Ab = A + (size_t)m0 * K + it * 64;
        const __half* Bb = B + (size_t)n0 * K + it * 64;
        unsigned da = smb + s * (G3_STAGE * 4);
        unsigned db = da + 4608 * 4;
#pragma unroll
        for (int p = 0; p < 4; p++) {
            int id = tid + p * 256;
            int row = id >> 3, o = id & 7;
            cpa16(da + row * 144u + o * 16u, Ab + (size_t)row * K + o * 8);
        }
#pragma unroll
        for (int p = 0; p < 4; p++) {
            int id = tid + p * 256;
            int row = id >> 3, o = id & 7;
            cpa16(db + row * 144u + o * 16u, Bb + (size_t)row * K + o * 8);
        }
    };

    float acc[4][4][4];
#pragma unroll
    for (int i = 0; i < 4; i++)
#pragma unroll
        for (int j = 0; j < 4; j++)
#pragma unroll
            for (int r = 0; r < 4; r++) acc[i][j][r] = 0.0f;

    loadAB(0, 0); cp_commit();

    for (int it = 0; it < NK; it++) {
        const int s = it & 1;
        if (it + 1 < NK) { loadAB(it + 1, s ^ 1); cp_commit(); cp_wait1(); }
        else             { cp_wait0(); }
        __syncthreads();

        const unsigned ab = smb + s * (G3_STAGE * 4);
        const unsigned bb = ab + 4608 * 4;
#pragma unroll
        for (int ks = 0; ks < 4; ks++) {
            unsigned a[4][4], bq[2][4];
#pragma unroll
            for (int mi = 0; mi < 4; mi++)
                ldm4(a[mi], ab + ((wm * 64 + mi * 16 + arow) * 36 + ks * 8 + acol) * 4);
#pragma unroll
            for (int jp = 0; jp < 2; jp++)
                ldm4(bq[jp], bb + ((wn * 32 + jp * 16 + brow) * 36 + ks * 8 + bcol) * 4);
#pragma unroll
            for (int j = 0; j < 4; j++) {
                const unsigned* pb = &bq[j >> 1][(j & 1) * 2];
#pragma unroll
                for (int mi = 0; mi < 4; mi++)
                    mma_h(acc[mi][j], a[mi], pb);
            }
        }
        __syncthreads();
    }

    const int rq = lane >> 2, cq = lane & 3;
#pragma unroll
    for (int mi = 0; mi < 4; mi++) {
        int r = m0 + wm * 64 + mi * 16 + rq;
#pragma unroll
        for (int j = 0; j < 4; j++) {
            int cn = n0 + wn * 32 + j * 8 + 2 * cq;
            *(float2*)&C[(size_t)r * N + cn]       = make_float2(acc[mi][j][0], acc[mi][j][1]);
            *(float2*)&C[(size_t)(r + 8) * N + cn] = make_float2(acc[mi][j][2], acc[mi][j][3]);
        }
    }
}

// -------------------- flash attention: 1 q-tile/block, 4 warps, 2-stage KV -----------
// 256 blocks x 128 threads. bid: h = bid&7, qt = 31 - (bid>>3)  (heavy first).
// SMEM u32: Q @0 [4352] | K stage s @ 4352+s*4352 | V stage s @ 13056+s*4608 ; 22272 wds.
#define ATT_SMEM_BYTES (22272 * 4)

__global__ __launch_bounds__(128, 2)
void attn_h()
{
    extern __shared__ unsigned sm[];
    const unsigned smb = smem_u32(sm);
    const int tid  = threadIdx.x;
    const int lane = tid & 31;
    const int w    = tid >> 5;
    const int rq   = lane >> 2;
    const int cq   = lane & 3;
    const int h    = blockIdx.x & 7;
    const int qt   = 31 - (blockIdx.x >> 3);
    const int q0   = qt * 64;

    const __half* qh = g_qh + (size_t)h * T_SEQ * HD;
    const __half* kh = g_kh + (size_t)h * T_SEQ * HD;
    const __half* vt = g_vt + (size_t)h * HD * T_SEQ;

    const int arow = (lane & 7) + ((lane >> 3) & 1) * 8;
    const int acol = (lane >> 4) * 4;
    const int brow = (lane & 7) + ((lane >> 4) & 1) * 8;
    const int bcol = ((lane >> 3) & 1) * 4;

    auto loadKV = [&](int t, int s) {
        const int s0 = t * 64;
        const unsigned kb = smb + (4352u + s * 4352u) * 4u;
        const unsigned vb = smb + (13056u + s * 4608u) * 4u;
#pragma unroll
        for (int p = 0; p < 8; p++) {
            int id = tid + p * 128;
            int row = id >> 4, o = id & 15;
            cpa16(kb + row * 272u + o * 16u, kh + (size_t)(s0 + row) * HD + o * 8);
        }
#pragma unroll
        for (int p = 0; p < 8; p++) {
            int id = tid + p * 128;
            int d = id >> 3, o = id & 7;
            cpa16(vb + d * 144u + o * 16u, vt + (size_t)d * T_SEQ + s0 + o * 8);
        }
    };

    // prologue: Q + KV0 (one group)
#pragma unroll
    for (int p = 0; p < 8; p++) {
        int id = tid + p * 128;
        int row = id >> 4, o = id & 15;
        cpa16(smb + (row * 68u) * 4u + o * 16u, qh + (size_t)(q0 + row) * HD + o * 8);
    }
    loadKV(0, 0);
    cp_commit();
    cp_wait0();
    __syncthreads();

    unsigned qa[8][4];
#pragma unroll
    for (int ks = 0; ks < 8; ks++)
        ldm4(qa[ks], smb + ((w * 16 + arow) * 68u + ks * 8 + acol) * 4);

    float m0 = -INFINITY, m1 = -INFINITY, l0 = 0.0f, l1 = 0.0f;
    float O[16][4];
#pragma unroll
    for (int nf = 0; nf < 16; nf++)
#pragma unroll
        for (int r = 0; r < 4; r++) O[nf][r] = 0.0f;

    for (int t = 0; t <= qt; t++) {
        // prefetch next tile into the other stage (its readers finished last iter)
        if (t < qt) { loadKV(t + 1, (t + 1) & 1); cp_commit(); }

        const int s = t & 1;
        const unsigned kb = smb + (4352u + s * 4352u) * 4u;
        const unsigned vb = smb + (13056u + s * 4608u) * 4u;

        // ---- S = Q K^T  (Q pre-scaled by ATTN_SCALE*log2e) ----
        float sc[8][4];
#pragma unroll
        for (int nf = 0; nf < 8; nf++)
#pragma unroll
            for (int r = 0; r < 4; r++) sc[nf][r] = 0.0f;

#pragma unroll
        for (int ks = 0; ks < 8; ks++) {
#pragma unroll
            for (int np = 0; np < 4; np++) {
                unsigned kq[4];
                ldm4(kq, kb + ((np * 16 + brow) * 68u + ks * 8 + bcol) * 4);
                mma_h(sc[2 * np],     qa[ks], &kq[0]);
                mma_h(sc[2 * np + 1], qa[ks], &kq[2]);
            }
        }

        const int r0l = w * 16 + rq, r1l = r0l + 8;
        if (t == qt) {
#pragma unroll
            for (int nf = 0; nf < 8; nf++) {
                int c0 = nf * 8 + 2 * cq;
                if (c0     > r0l) sc[nf][0] = -INFINITY;
                if (c0 + 1 > r0l) sc[nf][1] = -INFINITY;
                if (c0     > r1l) sc[nf][2] = -INFINITY;
                if (c0 + 1 > r1l) sc[nf][3] = -INFINITY;
            }
        }

        // ---- warp-local row max ----
        float mx0 = -INFINITY, mx1 = -INFINITY;
#pragma unroll
        for (int nf = 0; nf < 8; nf++) {
            mx0 = fmaxf(mx0, fmaxf(sc[nf][0], sc[nf][1]));
            mx1 = fmaxf(mx1, fmaxf(sc[nf][2], sc[nf][3]));
        }
#pragma unroll
        for (int off = 1; off <= 2; off <<= 1) {
            mx0 = fmaxf(mx0, __shfl_xor_sync(0xffffffffu, mx0, off));
            mx1 = fmaxf(mx1, __shfl_xor_sync(0xffffffffu, mx1, off));
        }
        const float nm0 = fmaxf(m0, mx0);
        const float nm1 = fmaxf(m1, mx1);

        // ---- exp2, P in registers as fp16 fragments ----
        float rs0 = 0.0f, rs1 = 0.0f;
        unsigned ph[8][2];
#pragma unroll
        for (int nf = 0; nf < 8; nf++) {
            float p0 = exp2f(sc[nf][0] - nm0);
            float p1 = exp2f(sc[nf][1] - nm0);
            float p2 = exp2f(sc[nf][2] - nm1);
            float p3 = exp2f(sc[nf][3] - nm1);
            rs0 += p0 + p1;
            rs1 += p2 + p3;
            ph[nf][0] = packh2(p0, p1);
            ph[nf][1] = packh2(p2, p3);
        }
#pragma unroll
        for (int off = 1; off <= 2; off <<= 1) {
            rs0 += __shfl_xor_sync(0xffffffffu, rs0, off);
            rs1 += __shfl_xor_sync(0xffffffffu, rs1, off);
        }

        const float al0 = exp2f(m0 - nm0);
        const float al1 = exp2f(m1 - nm1);
        l0 = l0 * al0 + rs0;  m0 = nm0;
        l1 = l1 * al1 + rs1;  m1 = nm1;
#pragma unroll
        for (int nf = 0; nf < 16; nf++) {
            O[nf][0] *= al0; O[nf][1] *= al0;
            O[nf][2] *= al1; O[nf][3] *= al1;
        }

        // ---- O += P @ V ----
#pragma unroll
        for (int ks = 0; ks < 4; ks++) {
            unsigned a[4] = { ph[2 * ks][0], ph[2 * ks][1],
                              ph[2 * ks + 1][0], ph[2 * ks + 1][1] };
#pragma unroll
            for (int np = 0; np < 8; np++) {
                unsigned vq[4];
                ldm4(vq, vb + ((np * 16 + brow) * 36u + ks * 8 + bcol) * 4);
                mma_h(O[2 * np],     a, &vq[0]);
                mma_h(O[2 * np + 1], a, &vq[2]);
            }
        }

        // wait for next tile + guard stage reuse
        if (t < qt) { cp_wait0(); __syncthreads(); }
    }

    const float inv0 = 1.0f / l0;
    const float inv1 = 1.0f / l1;
    const int row0 = q0 + w * 16 + rq, row1 = row0 + 8;
#pragma unroll
    for (int nf = 0; nf < 16; nf++) {
        int col = h * HD + nf * 8 + 2 * cq;
        *(unsigned*)&g_yh[(size_t)row0 * DIM_ + col] = packh2(O[nf][0] * inv0, O[nf][1] * inv0);
        *(unsigned*)&g_yh[(size_t)row1 * DIM_ + col] = packh2(O[nf][2] * inv1, O[nf][3] * inv1);
    }
}

// -------------------- launch ---------------------------------------------------------
extern "C" void kernel_launch(void* const* d_in, const int* in_sizes, int n_in,
                              void* d_out, int out_size)
{
    const float* x        = (const float*)d_in[0];
    const float* ve       = (const float*)d_in[1];
    const float* qkv_w    = (const float*)d_in[2];
    const float* lambdas  = (const float*)d_in[3];
    const float* c_proj_w = (const float*)d_in[4];
    float* out = (float*)d_out;

    __half *p_xh, *p_wqkv, *p_wproj, *p_yh;
    cudaGetSymbolAddress((void**)&p_xh,    g_xh);
    cudaGetSymbolAddress((void**)&p_wqkv,  g_wqkv);
    cudaGetSymbolAddress((void**)&p_wproj, g_wproj);
    cudaGetSymbolAddress((void**)&p_yh,    g_yh);

    // 0) fused converts + fr table, then rotary table
    prep<<<3073, 256>>>(x, qkv_w, c_proj_w);
    rot_build<<<256, 256>>>();

    // 1) QKV projection with fused rmsnorm/rotary(+C_SC on q)/vmix epilogue
    cudaFuncSetAttribute(gemm_qkv, cudaFuncAttributeMaxDynamicSharedMemorySize, GEMM_SMEM_BYTES);
    gemm_qkv<<<dim3(24, T_SEQ / 128), 256, GEMM_SMEM_BYTES>>>(p_xh, p_wqkv, ve, lambdas);

    // 2) causal flash attention -> fp16 g_yh  (256 blocks, 2 CTAs/SM)
    cudaFuncSetAttribute(attn_h, cudaFuncAttributeMaxDynamicSharedMemorySize, ATT_SMEM_BYTES);
    attn_h<<<dim3(256), 128, ATT_SMEM_BYTES>>>();

    // 3) output projection: out = yh @ wproj^T
    cudaFuncSetAttribute(gemm_h3, cudaFuncAttributeMaxDynamicSharedMemorySize, GEMM_SMEM_BYTES);
    gemm_h3<<<dim3(DIM_ / 128, T_SEQ / 128), 256, GEMM_SMEM_BYTES>>>(
        p_yh, p_wproj, out, T_SEQ, DIM_, DIM_);
}

// round 17
// speedup vs baseline: 1.0501x; 1.0501x over previous
#include <cuda_runtime.h>
#include <cuda_fp16.h>
#include <math.h>

#define T_SEQ 2048
#define DIM_   1024
#define NH     8
#define HD     128
#define RMS_EPS 1.1920929e-7f
#define C_SC (0.12f * 1.4426950408889634f)   // ATTN_SCALE * log2(e)

// -------------------- scratch (static device globals; no allocs) --------------------
__device__ __half g_xh   [(size_t)T_SEQ * DIM_];      // fp16 x
__device__ __half g_wqkv [(size_t)3 * DIM_ * DIM_];   // fp16 qkv_w
__device__ __half g_wproj[(size_t)DIM_ * DIM_];       // fp16 c_proj_w
__device__ __half g_qh   [(size_t)NH * T_SEQ * HD];   // [h][t][d]  (pre-scaled by C_SC)
__device__ __half g_kh   [(size_t)NH * T_SEQ * HD];   // [h][t][d]
__device__ __half g_vt   [(size_t)NH * HD * T_SEQ];   // [h][d][t]
__device__ __half g_yh   [(size_t)T_SEQ * DIM_];      // attention out, fp16
__device__ float  g_rot  [(size_t)T_SEQ * 64];        // [t][2j]=cos, [t][2j+1]=sin, j<32
__device__ float  g_fr   [32];                        // rotary frequencies

// -------------------- helpers --------------------------------------------------------
__device__ __forceinline__ uint2 f4h(float4 v) {
    uint2 r;
    asm("cvt.rn.f16x2.f32 %0, %1, %2;" : "=r"(r.x) : "f"(v.y), "f"(v.x));
    asm("cvt.rn.f16x2.f32 %0, %1, %2;" : "=r"(r.y) : "f"(v.w), "f"(v.z));
    return r;
}
__device__ __forceinline__ unsigned packh2(float lo, float hi) {
    unsigned r;
    asm("cvt.rn.f16x2.f32 %0, %1, %2;" : "=r"(r) : "f"(hi), "f"(lo));
    return r;
}
__device__ __forceinline__ void mma_h(float c[4], const unsigned a[4], const unsigned* b) {
    asm volatile(
        "mma.sync.aligned.m16n8k16.row.col.f32.f16.f16.f32 "
        "{%0,%1,%2,%3}, {%4,%5,%6,%7}, {%8,%9}, {%0,%1,%2,%3};"
        : "+f"(c[0]), "+f"(c[1]), "+f"(c[2]), "+f"(c[3])
        : "r"(a[0]), "r"(a[1]), "r"(a[2]), "r"(a[3]), "r"(b[0]), "r"(b[1]));
}
__device__ __forceinline__ void ldm4(unsigned r[4], unsigned addr) {
    asm volatile("ldmatrix.sync.aligned.m8n8.x4.shared.b16 {%0,%1,%2,%3}, [%4];"
                 : "=r"(r[0]), "=r"(r[1]), "=r"(r[2]), "=r"(r[3]) : "r"(addr));
}
__device__ __forceinline__ unsigned smem_u32(const void* p) {
    unsigned a;
    asm("{.reg .u64 t; cvta.to.shared.u64 t, %1; cvt.u32.u64 %0, t;}" : "=r"(a) : "l"(p));
    return a;
}
__device__ __forceinline__ void cpa16(unsigned dst, const void* src) {
    asm volatile("cp.async.cg.shared.global [%0], [%1], 16;" :: "r"(dst), "l"(src) : "memory");
}
__device__ __forceinline__ void cp_commit() { asm volatile("cp.async.commit_group;" ::: "memory"); }
__device__ __forceinline__ void cp_wait0()  { asm volatile("cp.async.wait_group 0;" ::: "memory"); }
__device__ __forceinline__ void cp_wait1()  { asm volatile("cp.async.wait_group 1;" ::: "memory"); }

// -------------------- fused prep: fp32->fp16 x/w_qkv/w_proj + fr table ----------------
__global__ __launch_bounds__(256)
void prep(const float* __restrict__ x, const float* __restrict__ qkv_w,
          const float* __restrict__ c_proj_w)
{
    const int b = blockIdx.x;
    const float* s;
    __half* d;
    int base;
    if (b < 1024)      { s = x;        d = g_xh;    base = b; }
    else if (b < 2560) { s = qkv_w;    d = g_wqkv;  base = b - 1024; }
    else if (b < 3072) { s = c_proj_w; d = g_wproj; base = b - 2560; }
    else {
        if (threadIdx.x < 32) {
            float tj = (float)threadIdx.x / 31.0f;
            g_fr[threadIdx.x] = (float)exp2(-10.0 * (double)tj);  // bit-identical fr
        }
        return;
    }
    int i = (base * 256 + threadIdx.x) * 8;
    float4 a = *(const float4*)(s + i);
    float4 c = *(const float4*)(s + i + 4);
    uint2 ua = f4h(a), uc = f4h(c);
    *(uint4*)(d + i) = make_uint4(ua.x, ua.y, uc.x, uc.y);
}

// -------------------- rotary table: fp32 Cody-Waite sincos ---------------------------
__global__ __launch_bounds__(256)
void rot_build()
{
    int idx = blockIdx.x * 256 + threadIdx.x;
    int t = idx >> 5, j = idx & 31;
    float th = (float)t * g_fr[j];

    const float C1 = 1.5703125f;
    const float C2 = 4.83826794897e-4f;
    float kf = rintf(th * 0.63661977236758134f);
    int   ki = (int)kf;
    float r  = fmaf(-kf, C1, th);
    r = fmaf(-kf, C2, r);

    float r2 = r * r;
    float sp = fmaf(r2, fmaf(r2, fmaf(r2, 2.75573137e-6f, -1.98412698e-4f),
                             8.33333376e-3f), -1.66666672e-1f);
    sp = fmaf(r * r2, sp, r);
    float cp = fmaf(r2, fmaf(r2, fmaf(r2, fmaf(r2, 2.44331571e-5f, -1.38873162e-3f),
                             4.16666418e-2f), -0.5f), 1.0f);

    float cosv, sinv;
    switch (ki & 3) {
        case 0:  cosv =  cp; sinv =  sp; break;
        case 1:  cosv = -sp; sinv =  cp; break;
        case 2:  cosv = -cp; sinv = -sp; break;
        default: cosv =  sp; sinv = -cp; break;
    }
    g_rot[t * 64 + 2 * j]     = cosv;
    g_rot[t * 64 + 2 * j + 1] = sinv;
}

// -------------------- fused QKV GEMM + rmsnorm/rotary/vmix epilogue ------------------
#define G3_STAGE 9216
#define GEMM_SMEM_BYTES (2 * G3_STAGE * 4)

__global__ __launch_bounds__(256, 2)
void gemm_qkv(const __half* __restrict__ A, const __half* __restrict__ B,
              const float* __restrict__ ve, const float* __restrict__ lambdas)
{
    extern __shared__ unsigned gsm[];
    const unsigned smb = smem_u32(gsm);
    const int tid  = threadIdx.x;
    const int lane = tid & 31;
    const int wid  = tid >> 5;
    const int wm   = wid >> 2;
    const int wn   = wid & 3;
    const int m0   = blockIdx.y * 128;
    const int n0   = blockIdx.x * 128;
    const int type = blockIdx.x >> 3;
    const int head = blockIdx.x & 7;
    const int K    = DIM_;
    const int rq   = lane >> 2, cq = lane & 3;

    const int arow = (lane & 7) + ((lane >> 3) & 1) * 8;
    const int acol = (lane >> 4) * 4;
    const int brow = (lane & 7) + ((lane >> 4) & 1) * 8;
    const int bcol = ((lane >> 3) & 1) * 4;
    const int NK   = K >> 6;

    auto loadAB = [&](int it, int s) {
        const __half* Ab = A + (size_t)m0 * K + it * 64;
        const __half* Bb = B + (size_t)n0 * K + it * 64;
        unsigned da = smb + s * (G3_STAGE * 4);
        unsigned db = da + 4608 * 4;
#pragma unroll
        for (int p = 0; p < 4; p++) {
            int id = tid + p * 256;
            int row = id >> 3, o = id & 7;
            cpa16(da + row * 144u + o * 16u, Ab + (size_t)row * K + o * 8);
        }
#pragma unroll
        for (int p = 0; p < 4; p++) {
            int id = tid + p * 256;
            int row = id >> 3, o = id & 7;
            cpa16(db + row * 144u + o * 16u, Bb + (size_t)row * K + o * 8);
        }
    };

    float acc[4][4][4];
#pragma unroll
    for (int i = 0; i < 4; i++)
#pragma unroll
        for (int j = 0; j < 4; j++)
#pragma unroll
            for (int r = 0; r < 4; r++) acc[i][j][r] = 0.0f;

    loadAB(0, 0); cp_commit();

    for (int it = 0; it < NK; it++) {
        const int s = it & 1;
        if (it + 1 < NK) { loadAB(it + 1, s ^ 1); cp_commit(); cp_wait1(); }
        else             { cp_wait0(); }
        __syncthreads();

        const unsigned ab = smb + s * (G3_STAGE * 4);
        const unsigned bb = ab + 4608 * 4;
#pragma unroll
        for (int ks = 0; ks < 4; ks++) {
            unsigned a[4][4], bq[2][4];
#pragma unroll
            for (int mi = 0; mi < 4; mi++)
                ldm4(a[mi], ab + ((wm * 64 + mi * 16 + arow) * 36 + ks * 8 + acol) * 4);
#pragma unroll
            for (int jp = 0; jp < 2; jp++)
                ldm4(bq[jp], bb + ((wn * 32 + jp * 16 + brow) * 36 + ks * 8 + bcol) * 4);
#pragma unroll
            for (int j = 0; j < 4; j++) {
                const unsigned* pb = &bq[j >> 1][(j & 1) * 2];
#pragma unroll
                for (int mi = 0; mi < 4; mi++)
                    mma_h(acc[mi][j], a[mi], pb);
            }
        }
        __syncthreads();
    }

    // ---------------- fused epilogue ----------------
    if (type < 2) {
        float* stageF = (float*)gsm;                 // [128][132]
        float* red    = (float*)gsm + 16896;         // [4][128]

#pragma unroll
        for (int mi = 0; mi < 4; mi++) {
            float p0 = 0.0f, p1 = 0.0f;
#pragma unroll
            for (int j = 0; j < 4; j++) {
                p0 = fmaf(acc[mi][j][0], acc[mi][j][0], p0);
                p0 = fmaf(acc[mi][j][1], acc[mi][j][1], p0);
                p1 = fmaf(acc[mi][j][2], acc[mi][j][2], p1);
                p1 = fmaf(acc[mi][j][3], acc[mi][j][3], p1);
            }
            p0 += __shfl_xor_sync(0xffffffffu, p0, 1);
            p0 += __shfl_xor_sync(0xffffffffu, p0, 2);
            p1 += __shfl_xor_sync(0xffffffffu, p1, 1);
            p1 += __shfl_xor_sync(0xffffffffu, p1, 2);
            if (cq == 0) {
                int row = wm * 64 + mi * 16 + rq;
                red[wn * 128 + row]     = p0;
                red[wn * 128 + row + 8] = p1;
            }
        }
        __syncthreads();

#pragma unroll
        for (int mi = 0; mi < 4; mi++) {
            int row0 = wm * 64 + mi * 16 + rq;
            float s0 = red[row0] + red[128 + row0] + red[256 + row0] + red[384 + row0];
            float s1 = red[row0 + 8] + red[128 + row0 + 8] + red[256 + row0 + 8] + red[384 + row0 + 8];
            float rn0 = rsqrtf(s0 * (1.0f / 128.0f) + RMS_EPS);
            float rn1 = rsqrtf(s1 * (1.0f / 128.0f) + RMS_EPS);
#pragma unroll
            for (int j = 0; j < 4; j++) {
                acc[mi][j][0] *= rn0; acc[mi][j][1] *= rn0;
                acc[mi][j][2] *= rn1; acc[mi][j][3] *= rn1;
            }
        }
        __syncthreads();

#pragma unroll
        for (int mi = 0; mi < 4; mi++) {
            int row0 = wm * 64 + mi * 16 + rq, row1 = row0 + 8;
            int c = wn * 32 + 2 * cq;
#pragma unroll
            for (int j = 0; j < 4; j++) {
                *(float2*)&stageF[row0 * 132 + c + j * 8] = make_float2(acc[mi][j][0], acc[mi][j][1]);
                *(float2*)&stageF[row1 * 132 + c + j * 8] = make_float2(acc[mi][j][2], acc[mi][j][3]);
            }
        }
        __syncthreads();

        __half* dst = (type == 0 ? g_qh : g_kh) + (size_t)head * T_SEQ * HD;
        const float osc = (type == 0) ? C_SC : 1.0f;   // pre-scale q into log2 domain
        const bool dorot = ((wn & 1) == 0);
        const float sgn = (wn == 0) ? 1.0f : -1.0f;
#pragma unroll
        for (int mi = 0; mi < 4; mi++) {
#pragma unroll
            for (int p = 0; p < 2; p++) {
                int row_l = wm * 64 + mi * 16 + rq + p * 8;
                int row_g = m0 + row_l;
#pragma unroll
                for (int j = 0; j < 4; j++) {
                    int c = wn * 32 + j * 8 + 2 * cq;
                    float v0 = acc[mi][j][2 * p], v1 = acc[mi][j][2 * p + 1];
                    float o0 = v0, o1 = v1;
                    if (dorot) {
                        float2 pp = *(float2*)&stageF[row_l * 132 + (c ^ 64)];
                        float4 cs = *(const float4*)&g_rot[(size_t)row_g * 64 + 2 * (c & 63)];
                        o0 = fmaf(sgn * pp.x, cs.y, v0 * cs.x);
                        o1 = fmaf(sgn * pp.y, cs.w, v1 * cs.z);
                    }
                    *(unsigned*)&dst[(size_t)row_g * HD + c] = packh2(o0 * osc, o1 * osc);
                }
            }
        }
    } else {
        const float l0v = lambdas[0], l1v = lambdas[1];
        __half* tile = (__half*)gsm;                 // [128][136]
#pragma unroll
        for (int mi = 0; mi < 4; mi++) {
            int row0 = wm * 64 + mi * 16 + rq, row1 = row0 + 8;
#pragma unroll
            for (int j = 0; j < 4; j++) {
                int c = wn * 32 + j * 8 + 2 * cq;
                float2 e0 = *(const float2*)&ve[(size_t)(m0 + row0) * DIM_ + head * HD + c];
                float2 e1 = *(const float2*)&ve[(size_t)(m0 + row1) * DIM_ + head * HD + c];
                *(unsigned*)&tile[row0 * 136 + c] =
                    packh2(fmaf(l1v, e0.x, l0v * acc[mi][j][0]), fmaf(l1v, e0.y, l0v * acc[mi][j][1]));
                *(unsigned*)&tile[row1 * 136 + c] =
                    packh2(fmaf(l1v, e1.x, l0v * acc[mi][j][2]), fmaf(l1v, e1.y, l0v * acc[mi][j][3]));
            }
        }
        __syncthreads();
#pragma unroll
        for (int p = 0; p < 8; p++) {
            int id = tid + p * 256;
            int d = id >> 4, t8 = (id & 15) * 8;
            __half tmp[8];
#pragma unroll
            for (int i = 0; i < 8; i++) tmp[i] = tile[(t8 + i) * 136 + d];
            *(uint4*)&g_vt[((size_t)head * HD + d) * T_SEQ + m0 + t8] = *(uint4*)tmp;
        }
    }
}

// -------------------- plain GEMM (fp16 TC, 2-stage): C = A @ B^T (proj) --------------
__global__ __launch_bounds__(256, 2)
void gemm_h3(const __half* __restrict__ A, const __half* __restrict__ B,
             float* __restrict__ C, int M, int N, int K)
{
    extern __shared__ unsigned gsm[];
    const unsigned smb = smem_u32(gsm);
    const int tid  = threadIdx.x;
    const int lane = tid & 31;
    const int wid  = tid >> 5;
    const int wm   = wid >> 2;
    const int wn   = wid & 3;
    const int m0   = blockIdx.y * 128;
    const int n0   = blockIdx.x * 128;

    const int arow = (lane & 7) + ((lane >> 3) & 1) * 8;
    const int acol = (lane >> 4) * 4;
    const int brow = (lane & 7) + ((lane >> 4) & 1) * 8;
    const int bcol = ((lane >> 3) & 1) * 4;
    const int NK   = K >> 6;

    auto loadAB = [&](int it, int s) {
        const __half* Ab = A + (size_t)m0 * K + it * 64;
        const __half* Bb = B + (size_t)n0 * K + it * 64;
        unsigned da = smb + s * (G3_STAGE * 4);
        unsigned db = da + 4608 * 4;
#pragma unroll
        for (int p = 0; p < 4; p++) {
            int id = tid + p * 256;
            int row = id >> 3, o = id & 7;
            cpa16(da + row * 144u + o * 16u, Ab + (size_t)row * K + o * 8);
        }
#pragma unroll
        for (int p = 0; p < 4; p++) {
            int id = tid + p * 256;
            int row = id >> 3, o = id & 7;
            cpa16(db + row * 144u + o * 16u, Bb + (size_t)row * K + o * 8);
        }
    };

    float acc[4][4][4];
#pragma unroll
    for (int i = 0; i < 4; i++)
#pragma unroll
        for (int j = 0; j < 4; j++)
#pragma unroll
            for (int r = 0; r < 4; r++) acc[i][j][r] = 0.0f;

    loadAB(0, 0); cp_commit();

    for (int it = 0; it < NK; it++) {
        const int s = it & 1;
        if (it + 1 < NK) { loadAB(it + 1, s ^ 1); cp_commit(); cp_wait1(); }
        else             { cp_wait0(); }
        __syncthreads();

        const unsigned ab = smb + s * (G3_STAGE * 4);
        const unsigned bb = ab + 4608 * 4;
#pragma unroll
        for (int ks = 0; ks < 4; ks++) {
            unsigned a[4][4], bq[2][4];
#pragma unroll
            for (int mi = 0; mi < 4; mi++)
                ldm4(a[mi], ab + ((wm * 64 + mi * 16 + arow) * 36 + ks * 8 + acol) * 4);
#pragma unroll
            for (int jp = 0; jp < 2; jp++)
                ldm4(bq[jp], bb + ((wn * 32 + jp * 16 + brow) * 36 + ks * 8 + bcol) * 4);
#pragma unroll
            for (int j = 0; j < 4; j++) {
                const unsigned* pb = &bq[j >> 1][(j & 1) * 2];
#pragma unroll
                for (int mi = 0; mi < 4; mi++)
                    mma_h(acc[mi][j], a[mi], pb);
            }
        }
        __syncthreads();
    }

    const int rq = lane >> 2, cq = lane & 3;
#pragma unroll
    for (int mi = 0; mi < 4; mi++) {
        int r = m0 + wm * 64 + mi * 16 + rq;
#pragma unroll
        for (int j = 0; j < 4; j++) {
            int cn = n0 + wn * 32 + j * 8 + 2 * cq;
            *(float2*)&C[(size_t)r * N + cn]       = make_float2(acc[mi][j][0], acc[mi][j][1]);
            *(float2*)&C[(size_t)(r + 8) * N + cn] = make_float2(acc[mi][j][2], acc[mi][j][3]);
        }
    }
}

// -------------------- flash attention: serial pair, BN=128, 2-stage KV ---------------
// 128 blocks x 128 threads. Block b: head = b&7, pr = b>>3; q-tiles {pr, 31-pr}.
// Per q-tile qt: ntk = ceil((qt+1)/2) KV tiles of 128 => 17 iterations per block total.
// SMEM u32: Q @0 [4352] | K stage s @ 4352+s*8704 | V stage s @ 21760+s*8704 ; 39168 wds.
#define ATT_SMEM_BYTES (39168 * 4)

__global__ __launch_bounds__(128, 1)
void attn_h()
{
    extern __shared__ unsigned sm[];
    const unsigned smb = smem_u32(sm);
    const int tid  = threadIdx.x;
    const int lane = tid & 31;
    const int w    = tid >> 5;
    const int rq   = lane >> 2;
    const int cq   = lane & 3;
    const int h    = blockIdx.x & 7;
    const int pr   = blockIdx.x >> 3;

    const __half* qh = g_qh + (size_t)h * T_SEQ * HD;
    const __half* kh = g_kh + (size_t)h * T_SEQ * HD;
    const __half* vt = g_vt + (size_t)h * HD * T_SEQ;

    const int arow = (lane & 7) + ((lane >> 3) & 1) * 8;
    const int acol = (lane >> 4) * 4;
    const int brow = (lane & 7) + ((lane >> 4) & 1) * 8;
    const int bcol = ((lane >> 3) & 1) * 4;

    auto loadKV = [&](int s0, int s) {
        const unsigned kb = smb + (4352u + s * 8704u) * 4u;
        const unsigned vb = smb + (21760u + s * 8704u) * 4u;
#pragma unroll
        for (int p = 0; p < 16; p++) {
            int id = tid + p * 128;
            int row = id >> 4, o = id & 15;
            cpa16(kb + row * 272u + o * 16u, kh + (size_t)(s0 + row) * HD + o * 8);
        }
#pragma unroll
        for (int p = 0; p < 16; p++) {
            int id = tid + p * 128;
            int d = id >> 4, o = id & 15;
            cpa16(vb + d * 272u + o * 16u, vt + (size_t)d * T_SEQ + s0 + o * 8);
        }
    };

    for (int half_i = 0; half_i < 2; half_i++) {
        const int qt  = half_i ? (31 - pr) : pr;
        const int q0  = qt * 64;
        const int ntk = (qt + 2) >> 1;          // ceil((qt+1)/2) 128-wide KV tiles

        if (half_i) __syncthreads();             // prior half done with all SMEM

        // prologue: Q + KV0
#pragma unroll
        for (int p = 0; p < 8; p++) {
            int id = tid + p * 128;
            int row = id >> 4, o = id & 15;
            cpa16(smb + row * 272u + o * 16u, qh + (size_t)(q0 + row) * HD + o * 8);
        }
        loadKV(0, 0);
        cp_commit();
        cp_wait0();
        __syncthreads();

        unsigned qa[8][4];
#pragma unroll
        for (int ks = 0; ks < 8; ks++)
            ldm4(qa[ks], smb + ((w * 16 + arow) * 68u + ks * 8 + acol) * 4);

        float m0 = -INFINITY, m1 = -INFINITY, l0 = 0.0f, l1 = 0.0f;
        float O[16][4];
#pragma unroll
        for (int nf = 0; nf < 16; nf++)
#pragma unroll
            for (int r = 0; r < 4; r++) O[nf][r] = 0.0f;

        for (int t = 0; t < ntk; t++) {
            if (t + 1 < ntk) { loadKV((t + 1) * 128, (t + 1) & 1); cp_commit(); }

            const int s = t & 1;
            const unsigned kb = smb + (4352u + s * 8704u) * 4u;
            const unsigned vb = smb + (21760u + s * 8704u) * 4u;

            // ---- S = Q K^T (Q pre-scaled); 64 rows x 128 cols ----
            float sc[16][4];
#pragma unroll
            for (int nf = 0; nf < 16; nf++)
#pragma unroll
                for (int r = 0; r < 4; r++) sc[nf][r] = 0.0f;

#pragma unroll
            for (int ks = 0; ks < 8; ks++) {
#pragma unroll
                for (int np = 0; np < 8; np++) {
                    unsigned kq[4];
                    ldm4(kq, kb + ((np * 16 + brow) * 68u + ks * 8 + bcol) * 4);
                    mma_h(sc[2 * np],     qa[ks], &kq[0]);
                    mma_h(sc[2 * np + 1], qa[ks], &kq[2]);
                }
            }

            const int r0l = w * 16 + rq, r1l = r0l + 8;
            if (t == ntk - 1) {
                const int off = q0 - t * 128;    // 0 or 64
#pragma unroll
                for (int nf = 0; nf < 16; nf++) {
                    int c0 = nf * 8 + 2 * cq;
                    if (c0     > off + r0l) sc[nf][0] = -INFINITY;
                    if (c0 + 1 > off + r0l) sc[nf][1] = -INFINITY;
                    if (c0     > off + r1l) sc[nf][2] = -INFINITY;
                    if (c0 + 1 > off + r1l) sc[nf][3] = -INFINITY;
                }
            }

            // ---- warp-local row max ----
            float mx0 = -INFINITY, mx1 = -INFINITY;
#pragma unroll
            for (int nf = 0; nf < 16; nf++) {
                mx0 = fmaxf(mx0, fmaxf(sc[nf][0], sc[nf][1]));
                mx1 = fmaxf(mx1, fmaxf(sc[nf][2], sc[nf][3]));
            }
#pragma unroll
            for (int off2 = 1; off2 <= 2; off2 <<= 1) {
                mx0 = fmaxf(mx0, __shfl_xor_sync(0xffffffffu, mx0, off2));
                mx1 = fmaxf(mx1, __shfl_xor_sync(0xffffffffu, mx1, off2));
            }
            const float nm0 = fmaxf(m0, mx0);
            const float nm1 = fmaxf(m1, mx1);

            // ---- exp2, P in registers ----
            float rs0 = 0.0f, rs1 = 0.0f;
            unsigned ph[16][2];
#pragma unroll
            for (int nf = 0; nf < 16; nf++) {
                float p0 = exp2f(sc[nf][0] - nm0);
                float p1 = exp2f(sc[nf][1] - nm0);
                float p2 = exp2f(sc[nf][2] - nm1);
                float p3 = exp2f(sc[nf][3] - nm1);
                rs0 += p0 + p1;
                rs1 += p2 + p3;
                ph[nf][0] = packh2(p0, p1);
                ph[nf][1] = packh2(p2, p3);
            }
#pragma unroll
            for (int off2 = 1; off2 <= 2; off2 <<= 1) {
                rs0 += __shfl_xor_sync(0xffffffffu, rs0, off2);
                rs1 += __shfl_xor_sync(0xffffffffu, rs1, off2);
            }

            const float al0 = exp2f(m0 - nm0);
            const float al1 = exp2f(m1 - nm1);
            l0 = l0 * al0 + rs0;  m0 = nm0;
            l1 = l1 * al1 + rs1;  m1 = nm1;
#pragma unroll
            for (int nf = 0; nf < 16; nf++) {
                O[nf][0] *= al0; O[nf][1] *= al0;
                O[nf][2] *= al1; O[nf][3] *= al1;
            }

            // ---- O += P @ V  (kv depth 128) ----
#pragma unroll
            for (int ks = 0; ks < 8; ks++) {
                unsigned a[4] = { ph[2 * ks][0], ph[2 * ks][1],
                                  ph[2 * ks + 1][0], ph[2 * ks + 1][1] };
#pragma unroll
                for (int np = 0; np < 8; np++) {
                    unsigned vq[4];
                    ldm4(vq, vb + ((np * 16 + brow) * 68u + ks * 8 + bcol) * 4);
                    mma_h(O[2 * np],     a, &vq[0]);
                    mma_h(O[2 * np + 1], a, &vq[2]);
                }
            }

            if (t + 1 < ntk) { cp_wait0(); __syncthreads(); }
        }

        // epilogue -> fp16 y
        const float inv0 = 1.0f / l0;
        const float inv1 = 1.0f / l1;
        const int row0 = q0 + w * 16 + rq, row1 = row0 + 8;
#pragma unroll
        for (int nf = 0; nf < 16; nf++) {
            int col = h * HD + nf * 8 + 2 * cq;
            *(unsigned*)&g_yh[(size_t)row0 * DIM_ + col] = packh2(O[nf][0] * inv0, O[nf][1] * inv0);
            *(unsigned*)&g_yh[(size_t)row1 * DIM_ + col] = packh2(O[nf][2] * inv1, O[nf][3] * inv1);
        }
    }
}

// -------------------- launch ---------------------------------------------------------
extern "C" void kernel_launch(void* const* d_in, const int* in_sizes, int n_in,
                              void* d_out, int out_size)
{
    const float* x        = (const float*)d_in[0];
    const float* ve       = (const float*)d_in[1];
    const float* qkv_w    = (const float*)d_in[2];
    const float* lambdas  = (const float*)d_in[3];
    const float* c_proj_w = (const float*)d_in[4];
    float* out = (float*)d_out;

    __half *p_xh, *p_wqkv, *p_wproj, *p_yh;
    cudaGetSymbolAddress((void**)&p_xh,    g_xh);
    cudaGetSymbolAddress((void**)&p_wqkv,  g_wqkv);
    cudaGetSymbolAddress((void**)&p_wproj, g_wproj);
    cudaGetSymbolAddress((void**)&p_yh,    g_yh);

    // 0) fused converts + fr table, then rotary table
    prep<<<3073, 256>>>(x, qkv_w, c_proj_w);
    rot_build<<<256, 256>>>();

    // 1) QKV projection with fused rmsnorm/rotary(+C_SC on q)/vmix epilogue
    cudaFuncSetAttribute(gemm_qkv, cudaFuncAttributeMaxDynamicSharedMemorySize, GEMM_SMEM_BYTES);
    gemm_qkv<<<dim3(24, T_SEQ / 128), 256, GEMM_SMEM_BYTES>>>(p_xh, p_wqkv, ve, lambdas);

    // 2) causal flash attention -> fp16 g_yh  (128 uniform blocks, BN=128)
    cudaFuncSetAttribute(attn_h, cudaFuncAttributeMaxDynamicSharedMemorySize, ATT_SMEM_BYTES);
    attn_h<<<dim3(128), 128, ATT_SMEM_BYTES>>>();

    // 3) output projection: out = yh @ wproj^T
    cudaFuncSetAttribute(gemm_h3, cudaFuncAttributeMaxDynamicSharedMemorySize, GEMM_SMEM_BYTES);
    gemm_h3<<<dim3(DIM_ / 128, T_SEQ / 128), 256, GEMM_SMEM_BYTES>>>(
        p_yh, p_wproj, out, T_SEQ, DIM_, DIM_);
}